// round 14
// baseline (speedup 1.0000x reference)
#include <cuda_runtime.h>

// ---------------- problem constants ----------------
#define BB 16          // batch
#define TT 20          // timesteps
#define HH 96
#define WW 96
#define CC 3           // in channels
#define FF 4           // filters
#define HP 95          // valid conv out
#define WP 95
#define PH 47          // pooled
#define PW 47
#define NPOS (HP*WP)   // 9025
#define NTHREADS 128   // threads per CTA; each thread owns 2 positions
#define POSPC 256      // positions per CTA
#define NBLKX 36       // ceil(9025 / 256)
#define NCTAS (NBLKX * BB)   // 576; 4 CTAs/SM * 148 = 592 slots -> all co-resident
#define HALO 97        // slots of each CTA read by blk-1 via global (+1,+95,+96)

// ---------------- persistent device scratch (no allocs allowed) ----------------
__device__ float g_h[2][BB * NPOS * FF];     // ping-pong hidden state (halo slots only are kept fresh)
__device__ float g_scratch[BB * NBLKX];      // per-block dense partial (written once)
__device__ unsigned g_flag[BB][NBLKX][8];    // per-CTA monotonic step flags (32B sectors)
__device__ unsigned g_done[BB];              // per-batch arrival counters (self-reset)

__device__ __forceinline__ float ftanh(float x) {
    float y;
    asm("tanh.approx.f32 %0, %1;" : "=f"(y) : "f"(x));
    return y;
}
__device__ __forceinline__ float fsig(float x) {
    return fmaf(ftanh(0.5f * x), 0.5f, 0.5f);
}

// ---- packed fp32x2 helpers (Blackwell dual-fp32 path; PTX-only) ----
__device__ __forceinline__ unsigned long long dup2(float v) {
    unsigned long long r;
    asm("mov.b64 %0, {%1, %1};" : "=l"(r) : "f"(v));
    return r;
}
__device__ __forceinline__ void fma2(unsigned long long& a,
                                     unsigned long long v, unsigned long long w) {
    asm("fma.rn.f32x2 %0, %1, %2, %0;" : "+l"(a) : "l"(v), "l"(w));
}
__device__ __forceinline__ float2 unpack2(unsigned long long a) {
    float lo, hi;
    asm("mov.b64 {%0, %1}, %2;" : "=f"(lo), "=f"(hi) : "l"(a));
    return make_float2(lo, hi);
}

// ---- gpu-scope release/acquire flag ops (CG grid-sync pattern) ----
__device__ __forceinline__ void st_release(unsigned* f, unsigned v) {
    asm volatile("st.release.gpu.u32 [%0], %1;" :: "l"(f), "r"(v) : "memory");
}
__device__ __forceinline__ unsigned ld_acquire(unsigned* f) {
    unsigned v;
    asm volatile("ld.acquire.gpu.u32 %0, [%1];" : "=r"(v) : "l"(f) : "memory");
    return v;
}
__device__ __forceinline__ void wait_flag(unsigned* f, unsigned target) {
    while ((int)(ld_acquire(f) - target) < 0) __nanosleep(20);
}

// bias + input conv (VALID) for BOTH positions; weights loaded once, shared.
// Runs in the neighbor-skew shadow after publishing the previous step.
__device__ __forceinline__ void input_conv2(
    unsigned long long zp0[8], unsigned long long zp1[8],
    const float* __restrict__ x, int b, int t,
    int i0, int j0, bool a0, int i1, int j1, bool a1,
    const float4* __restrict__ sK, const float4* __restrict__ sB)
{
    #pragma unroll
    for (int h = 0; h < 4; h++) {
        const ulonglong2 bb = ((const ulonglong2*)sB)[h];
        zp0[2 * h] = bb.x; zp0[2 * h + 1] = bb.y;
        zp1[2 * h] = bb.x; zp1[2 * h + 1] = bb.y;
    }
    float xv0[12], xv1[12];
    #pragma unroll
    for (int e = 0; e < 12; e++) { xv0[e] = 0.f; xv1[e] = 0.f; }
    if (a0) {
        const float* xb = x + ((((size_t)b * TT + t) * HH + i0) * WW + j0) * CC;
        #pragma unroll
        for (int q = 0; q < 4; q++)
            #pragma unroll
            for (int ci = 0; ci < CC; ci++)
                xv0[q * 3 + ci] = xb[((q >> 1) * WW + (q & 1)) * CC + ci];
    }
    if (a1) {
        const float* xb = x + ((((size_t)b * TT + t) * HH + i1) * WW + j1) * CC;
        #pragma unroll
        for (int q = 0; q < 4; q++)
            #pragma unroll
            for (int ci = 0; ci < CC; ci++)
                xv1[q * 3 + ci] = xb[((q >> 1) * WW + (q & 1)) * CC + ci];
    }
    #pragma unroll
    for (int e = 0; e < 12; e++) {
        const unsigned long long vv0 = dup2(xv0[e]);
        const unsigned long long vv1 = dup2(xv1[e]);
        const ulonglong2* kw = (const ulonglong2*)&sK[e * 4];
        #pragma unroll
        for (int h = 0; h < 4; h++) {
            const ulonglong2 w = kw[h];            // shared weight load
            fma2(zp0[2 * h],     vv0, w.x);
            fma2(zp0[2 * h + 1], vv0, w.y);
            fma2(zp1[2 * h],     vv1, w.x);
            fma2(zp1[2 * h + 1], vv1, w.y);
        }
    }
}

// Read h_{t-1} for local slot s (relative to this CTA's base):
// intra-CTA -> smem tile; beyond -> global (blk+1's halo, always stored).
__device__ __forceinline__ float4 h_read(int s, const float4* __restrict__ sprev,
                                         const float4* __restrict__ gprev) {
    return (s < POSPC) ? sprev[s] : gprev[s];
}

__global__ void __launch_bounds__(NTHREADS, 4)
persistent_kernel(const float* __restrict__ x,
                  const float4* __restrict__ Kw,    // 48 float4
                  const float4* __restrict__ RKw,   // 64 float4
                  const float4* __restrict__ bias,  // 4 float4
                  const float* __restrict__ dw,
                  const float* __restrict__ db,
                  float* __restrict__ out)
{
    __shared__ float4 sK[48];
    __shared__ float4 sRK[64];
    __shared__ float4 sB[4];
    __shared__ float4 sH[2][POSPC];          // double-buffered h tile (8 KB)
    __shared__ float warpsum[NTHREADS / 32];

    const int tid = threadIdx.x;
    const int b   = blockIdx.y;
    const int blk = blockIdx.x;

    // Monotonic base: own flag (written only by this CTA; +TT per replay).
    const unsigned base = ld_acquire(&g_flag[b][blk][0]);

    if (tid < 48) sK[tid]  = Kw[tid];
    if (tid < 64) sRK[tid] = RKw[tid];
    if (tid < 4)  sB[tid]  = bias[tid];
    __syncthreads();

    const int p0 = blk * POSPC + tid;
    const int p1 = p0 + NTHREADS;
    const bool a0 = (p0 < NPOS);
    const bool a1 = (p1 < NPOS);
    const int i0 = p0 / WP, j0 = p0 % WP;
    const int i1 = p1 / WP, j1 = p1 % WP;
    const int s1 = tid + NTHREADS;           // pos1 local slot

    // Thread-private recurrent state for both positions.
    float creg[2][4] = {{0.f,0.f,0.f,0.f},{0.f,0.f,0.f,0.f}};
    float hreg[2][4] = {{0.f,0.f,0.f,0.f},{0.f,0.f,0.f,0.f}};
    float dense_acc = 0.f;

    unsigned long long zp0[8], zp1[8];       // staged gate pre-activations
    input_conv2(zp0, zp1, x, b, 0, i0, j0, a0, i1, j1, a1, sK, sB);

    for (int t = 0; t < TT; t++) {
        if (t > 0) {
            // RAW: blk+1 finished step t-1 (we read its halo h).
            // WAR: blk-1 finished step t-1 (it read the h buffer we overwrite).
            if (tid == 0) {
                const unsigned tgt = base + (unsigned)t;
                if (blk > 0)         wait_flag(&g_flag[b][blk - 1][0], tgt);
                if (blk + 1 < NBLKX) wait_flag(&g_flag[b][blk + 1][0], tgt);
            }
            __syncthreads();   // also orders prev step's sH writes for reads below
        }

        float m[2][4];
        #pragma unroll
        for (int s = 0; s < 2; s++)
            #pragma unroll
            for (int f = 0; f < 4; f++) m[s][f] = hreg[s][f];

        if (t > 0) {
            const float4* sprev = sH[(t + 1) & 1];
            const float4* gprev = (const float4*)(g_h[(t + 1) & 1]
                                    + (size_t)b * NPOS * FF) + blk * POSPC;

            // q=0: own h_{t-1} (registers), weights shared across positions.
            #pragma unroll
            for (int f = 0; f < 4; f++) {
                const unsigned long long vv0 = dup2(hreg[0][f]);
                const unsigned long long vv1 = dup2(hreg[1][f]);
                const ulonglong2* rw = (const ulonglong2*)&sRK[f * 4];
                #pragma unroll
                for (int h = 0; h < 4; h++) {
                    const ulonglong2 w = rw[h];
                    fma2(zp0[2 * h],     vv0, w.x);
                    fma2(zp0[2 * h + 1], vv0, w.y);
                    fma2(zp1[2 * h],     vv1, w.x);
                    fma2(zp1[2 * h + 1], vv1, w.y);
                }
            }
            // q=1..3: neighbors via smem tile (or global halo), zeros OOB.
            #pragma unroll
            for (int q = 1; q < 4; q++) {
                const int di = q >> 1, dj = q & 1;
                const int off = di * WP + dj;          // +1, +95, +96
                float4 h40 = make_float4(0.f, 0.f, 0.f, 0.f);
                float4 h41 = make_float4(0.f, 0.f, 0.f, 0.f);
                if (a0 && (i0 + di) < HP && (j0 + dj) < WP)
                    h40 = h_read(tid + off, sprev, gprev);
                if (a1 && (i1 + di) < HP && (j1 + dj) < WP)
                    h41 = h_read(s1 + off, sprev, gprev);
                m[0][0] = fmaxf(m[0][0], h40.x); m[0][1] = fmaxf(m[0][1], h40.y);
                m[0][2] = fmaxf(m[0][2], h40.z); m[0][3] = fmaxf(m[0][3], h40.w);
                m[1][0] = fmaxf(m[1][0], h41.x); m[1][1] = fmaxf(m[1][1], h41.y);
                m[1][2] = fmaxf(m[1][2], h41.z); m[1][3] = fmaxf(m[1][3], h41.w);
                const float hv0[4] = {h40.x, h40.y, h40.z, h40.w};
                const float hv1[4] = {h41.x, h41.y, h41.z, h41.w};
                #pragma unroll
                for (int f = 0; f < 4; f++) {
                    const unsigned long long vv0 = dup2(hv0[f]);
                    const unsigned long long vv1 = dup2(hv1[f]);
                    const ulonglong2* rw = (const ulonglong2*)&sRK[(q * 4 + f) * 4];
                    #pragma unroll
                    for (int h = 0; h < 4; h++) {
                        const ulonglong2 w = rw[h];
                        fma2(zp0[2 * h],     vv0, w.x);
                        fma2(zp0[2 * h + 1], vv0, w.y);
                        fma2(zp1[2 * h],     vv1, w.x);
                        fma2(zp1[2 * h + 1], vv1, w.y);
                    }
                }
            }
        }

        // ---- gates (order i,f,g,o) + state update ----
        #pragma unroll
        for (int s = 0; s < 2; s++) {
            unsigned long long* zp = (s == 0) ? zp0 : zp1;
            const float2 a0v = unpack2(zp[0]), a1v = unpack2(zp[1]);
            const float2 b0v = unpack2(zp[2]), b1v = unpack2(zp[3]);
            const float2 c0v = unpack2(zp[4]), c1v = unpack2(zp[5]);
            const float2 d0v = unpack2(zp[6]), d1v = unpack2(zp[7]);
            const float zi[4] = {a0v.x, a0v.y, a1v.x, a1v.y};
            const float zf[4] = {b0v.x, b0v.y, b1v.x, b1v.y};
            const float zg[4] = {c0v.x, c0v.y, c1v.x, c1v.y};
            const float zo[4] = {d0v.x, d0v.y, d1v.x, d1v.y};
            #pragma unroll
            for (int f = 0; f < 4; f++) {
                const float ig = fsig(zi[f]);
                const float fg = fsig(zf[f]);
                const float gg = ftanh(zg[f]);
                const float og = fsig(zo[f]);
                const float c2 = fg * creg[s][f] + ig * gg;
                creg[s][f] = c2;
                hreg[s][f] = og * ftanh(c2);
            }
        }

        // h publication: smem tile for intra-CTA; global only for blk-1's halo.
        {
            float4* scur = sH[t & 1];
            scur[tid] = make_float4(hreg[0][0], hreg[0][1], hreg[0][2], hreg[0][3]);
            scur[s1]  = make_float4(hreg[1][0], hreg[1][1], hreg[1][2], hreg[1][3]);
            if (a0 && tid < HALO) {
                float* hnew = g_h[t & 1] + (size_t)b * NPOS * FF;
                *(float4*)(hnew + (size_t)p0 * 4) =
                    make_float4(hreg[0][0], hreg[0][1], hreg[0][2], hreg[0][3]);
            }
        }

        // ---- maxpool(2x2) + dense contribution of h_{t-1}, per position ----
        if (t > 0) {
            #pragma unroll
            for (int s = 0; s < 2; s++) {
                const int  is = (s == 0) ? i0 : i1;
                const int  js = (s == 0) ? j0 : j1;
                const bool as = (s == 0) ? a0 : a1;
                if (as && ((is & 1) | (js & 1)) == 0 && is < 94 && js < 94) {
                    const int ph = is >> 1, pw = js >> 1;
                    const float4 w4 = *(const float4*)(dw +
                        ((((size_t)(t - 1) * PH + ph) * PW + pw) * 4));
                    dense_acc += m[s][0] * w4.x + m[s][1] * w4.y
                               + m[s][2] * w4.z + m[s][3] * w4.w;
                }
            }
        }

        __syncthreads();   // all halo STGs + sH writes done before publish
        if (tid == 0)
            st_release(&g_flag[b][blk][0], base + (unsigned)(t + 1));

        // Stage step t+1's x-dependent work in the neighbor-skew shadow.
        if (t + 1 < TT)
            input_conv2(zp0, zp1, x, b, t + 1, i0, j0, a0, i1, j1, a1, sK, sB);
    }

    // Epilogue RAW: pool of h_{T-1}; own values in hreg, neighbors via tile/halo.
    if (tid == 0) {
        if (blk + 1 < NBLKX) wait_flag(&g_flag[b][blk + 1][0], base + TT);
    }
    __syncthreads();

    {
        const float4* slast = sH[(TT - 1) & 1];
        const float4* glast = (const float4*)(g_h[(TT - 1) & 1]
                                + (size_t)b * NPOS * FF) + blk * POSPC;
        #pragma unroll
        for (int s = 0; s < 2; s++) {
            const int  is = (s == 0) ? i0 : i1;
            const int  js = (s == 0) ? j0 : j1;
            const int  ss = (s == 0) ? tid : s1;
            const bool as = (s == 0) ? a0 : a1;
            if (as && ((is & 1) | (js & 1)) == 0 && is < 94 && js < 94) {
                float m0 = hreg[s][0], m1 = hreg[s][1], m2 = hreg[s][2], m3 = hreg[s][3];
                #pragma unroll
                for (int q = 1; q < 4; q++) {
                    const int off = (q >> 1) * WP + (q & 1);
                    const float4 h4 = h_read(ss + off, slast, glast);
                    m0 = fmaxf(m0, h4.x); m1 = fmaxf(m1, h4.y);
                    m2 = fmaxf(m2, h4.z); m3 = fmaxf(m3, h4.w);
                }
                const int ph = is >> 1, pw = js >> 1;
                const float4 w4 = *(const float4*)(dw +
                    ((((size_t)(TT - 1) * PH + ph) * PW + pw) * 4));
                dense_acc += m0 * w4.x + m1 * w4.y + m2 * w4.z + m3 * w4.w;
            }
        }
    }

    // Deterministic block reduction -> one scratch write per CTA.
    #pragma unroll
    for (int off = 16; off > 0; off >>= 1)
        dense_acc += __shfl_down_sync(0xFFFFFFFFu, dense_acc, off);
    if ((tid & 31) == 0) warpsum[tid >> 5] = dense_acc;
    __syncthreads();
    if (tid == 0) {
        float s = 0.f;
        #pragma unroll
        for (int w = 0; w < NTHREADS / 32; w++) s += warpsum[w];
        g_scratch[b * NBLKX + blk] = s;

        // Per-batch completion: last CTA of batch b emits out[b].
        __threadfence();
        const unsigned old = atomicAdd(&g_done[b], 1u);
        if (old == (unsigned)(NBLKX - 1)) {
            atomicExch(&g_done[b], 0u);   // self-reset for next replay
            __threadfence();
            float acc = 0.f;
            for (int k = 0; k < NBLKX; k++) acc += g_scratch[b * NBLKX + k];
            out[b] = acc + db[0];
        }
    }
}

extern "C" void kernel_launch(void* const* d_in, const int* in_sizes, int n_in,
                              void* d_out, int out_size) {
    const float*  x    = (const float*)d_in[0];
    const float4* Kw   = (const float4*)d_in[1];
    const float4* RKw  = (const float4*)d_in[2];
    const float4* bias = (const float4*)d_in[3];
    const float*  dw   = (const float*)d_in[4];
    const float*  db   = (const float*)d_in[5];
    float* out = (float*)d_out;

    dim3 grid(NBLKX, BB);
    persistent_kernel<<<grid, NTHREADS>>>(x, Kw, RKw, bias, dw, db, out);
}

// round 17
// speedup vs baseline: 1.1290x; 1.1290x over previous
#include <cuda_runtime.h>

// ---------------- problem constants ----------------
#define BB 16          // batch
#define TT 20          // timesteps
#define HH 96
#define WW 96
#define CC 3           // in channels
#define FF 4           // filters
#define HP 95          // valid conv out
#define WP 95
#define PH 47          // pooled
#define PW 47
#define W96 96         // padded h row stride (col 95 + row 95 are zero pads)
#define SLOTS (W96*W96)      // 9216 = 36 * 256 exactly
#define NTHREADS 128   // threads per CTA; each thread owns 2 slots
#define POSPC 256      // slots per CTA
#define NBLKX 36
#define NCTAS (NBLKX * BB)   // 576; 4 CTAs/SM * 148 = 592 slots -> all co-resident

// ---------------- persistent device scratch (no allocs allowed) ----------------
// Padded layout: slot = i*96 + j. Pads (j==95 or i==95) are never written and
// start zero (device globals) -> they ARE the SAME-conv zero padding, forever.
__device__ float g_h[2][BB * SLOTS * FF];    // ping-pong hidden state
__device__ float g_scratch[BB * NBLKX];      // per-block dense partial (written once)
__device__ unsigned g_flag[BB][NBLKX][8];    // per-CTA monotonic step flags (32B sectors)
__device__ unsigned g_done[BB];              // per-batch arrival counters (self-reset)

__device__ __forceinline__ float ftanh(float x) {
    float y;
    asm("tanh.approx.f32 %0, %1;" : "=f"(y) : "f"(x));
    return y;
}
__device__ __forceinline__ float fsig(float x) {
    return fmaf(ftanh(0.5f * x), 0.5f, 0.5f);
}

// ---- packed fp32x2 helpers (Blackwell dual-fp32 path; PTX-only) ----
__device__ __forceinline__ unsigned long long dup2(float v) {
    unsigned long long r;
    asm("mov.b64 %0, {%1, %1};" : "=l"(r) : "f"(v));
    return r;
}
__device__ __forceinline__ void fma2(unsigned long long& a,
                                     unsigned long long v, unsigned long long w) {
    asm("fma.rn.f32x2 %0, %1, %2, %0;" : "+l"(a) : "l"(v), "l"(w));
}
__device__ __forceinline__ float2 unpack2(unsigned long long a) {
    float lo, hi;
    asm("mov.b64 {%0, %1}, %2;" : "=f"(lo), "=f"(hi) : "l"(a));
    return make_float2(lo, hi);
}

// ---- gpu-scope release/acquire flag ops (CG grid-sync pattern) ----
__device__ __forceinline__ void st_release(unsigned* f, unsigned v) {
    asm volatile("st.release.gpu.u32 [%0], %1;" :: "l"(f), "r"(v) : "memory");
}
__device__ __forceinline__ unsigned ld_acquire(unsigned* f) {
    unsigned v;
    asm volatile("ld.acquire.gpu.u32 %0, [%1];" : "=r"(v) : "l"(f) : "memory");
    return v;
}
__device__ __forceinline__ void wait_flag(unsigned* f, unsigned target) {
    while ((int)(ld_acquire(f) - target) < 0) __nanosleep(20);
}

// bias + input conv (VALID) for BOTH positions; weights loaded once, shared.
// Runs in the neighbor-skew shadow after publishing the previous step.
__device__ __forceinline__ void input_conv2(
    unsigned long long zp0[8], unsigned long long zp1[8],
    const float* __restrict__ x, int b, int t,
    int i0, int j0, bool a0, int i1, int j1, bool a1,
    const float4* __restrict__ sK, const float4* __restrict__ sB)
{
    #pragma unroll
    for (int h = 0; h < 4; h++) {
        const ulonglong2 bb = ((const ulonglong2*)sB)[h];
        zp0[2 * h] = bb.x; zp0[2 * h + 1] = bb.y;
        zp1[2 * h] = bb.x; zp1[2 * h + 1] = bb.y;
    }
    float xv0[12], xv1[12];
    #pragma unroll
    for (int e = 0; e < 12; e++) { xv0[e] = 0.f; xv1[e] = 0.f; }
    if (a0) {
        const float* xb = x + ((((size_t)b * TT + t) * HH + i0) * WW + j0) * CC;
        #pragma unroll
        for (int q = 0; q < 4; q++)
            #pragma unroll
            for (int ci = 0; ci < CC; ci++)
                xv0[q * 3 + ci] = xb[((q >> 1) * WW + (q & 1)) * CC + ci];
    }
    if (a1) {
        const float* xb = x + ((((size_t)b * TT + t) * HH + i1) * WW + j1) * CC;
        #pragma unroll
        for (int q = 0; q < 4; q++)
            #pragma unroll
            for (int ci = 0; ci < CC; ci++)
                xv1[q * 3 + ci] = xb[((q >> 1) * WW + (q & 1)) * CC + ci];
    }
    #pragma unroll
    for (int e = 0; e < 12; e++) {
        const unsigned long long vv0 = dup2(xv0[e]);
        const unsigned long long vv1 = dup2(xv1[e]);
        const ulonglong2* kw = (const ulonglong2*)&sK[e * 4];
        #pragma unroll
        for (int h = 0; h < 4; h++) {
            const ulonglong2 w = kw[h];            // shared weight load
            fma2(zp0[2 * h],     vv0, w.x);
            fma2(zp0[2 * h + 1], vv0, w.y);
            fma2(zp1[2 * h],     vv1, w.x);
            fma2(zp1[2 * h + 1], vv1, w.y);
        }
    }
}

__global__ void __launch_bounds__(NTHREADS, 4)
persistent_kernel(const float* __restrict__ x,
                  const float4* __restrict__ Kw,    // 48 float4
                  const float4* __restrict__ RKw,   // 64 float4
                  const float4* __restrict__ bias,  // 4 float4
                  const float* __restrict__ dw,
                  const float* __restrict__ db,
                  float* __restrict__ out)
{
    __shared__ float4 sK[48];
    __shared__ float4 sRK[64];
    __shared__ float4 sB[4];
    __shared__ float warpsum[NTHREADS / 32];

    const int tid = threadIdx.x;
    const int b   = blockIdx.y;
    const int blk = blockIdx.x;

    // Monotonic base: own flag (written only by this CTA; +TT per replay).
    const unsigned base = ld_acquire(&g_flag[b][blk][0]);

    if (tid < 48) sK[tid]  = Kw[tid];
    if (tid < 64) sRK[tid] = RKw[tid];
    if (tid < 4)  sB[tid]  = bias[tid];
    __syncthreads();

    const int p0 = blk * POSPC + tid;        // slot in padded 96x96 layout
    const int p1 = p0 + NTHREADS;
    const int i0 = p0 / W96, j0 = p0 % W96;
    const int i1 = p1 / W96, j1 = p1 % W96;
    const bool a0 = (i0 < HP) && (j0 < WP);  // pad slots are inactive
    const bool a1 = (i1 < HP) && (j1 < WP);

    // Thread-private recurrent state for both positions.
    float creg[2][4] = {{0.f,0.f,0.f,0.f},{0.f,0.f,0.f,0.f}};
    float hreg[2][4] = {{0.f,0.f,0.f,0.f},{0.f,0.f,0.f,0.f}};
    float dense_acc = 0.f;

    unsigned long long zp0[8], zp1[8];       // staged gate pre-activations
    input_conv2(zp0, zp1, x, b, 0, i0, j0, a0, i1, j1, a1, sK, sB);

    for (int t = 0; t < TT; t++) {
        if (t > 0) {
            // RAW: blk+1 finished step t-1 (we read its h slots, offset <= +97).
            // WAR: blk-1 finished step t-1 (it read the h buffer we overwrite).
            if (tid == 0) {
                const unsigned tgt = base + (unsigned)t;
                if (blk > 0)         wait_flag(&g_flag[b][blk - 1][0], tgt);
                if (blk + 1 < NBLKX) wait_flag(&g_flag[b][blk + 1][0], tgt);
            }
            __syncthreads();
        }

        float m[2][4];
        #pragma unroll
        for (int s = 0; s < 2; s++)
            #pragma unroll
            for (int f = 0; f < 4; f++) m[s][f] = hreg[s][f];

        if (t > 0) {
            const float* hprev = g_h[(t + 1) & 1] + (size_t)b * SLOTS * FF;

            // q=0: own h_{t-1} (registers), weights shared across positions.
            #pragma unroll
            for (int f = 0; f < 4; f++) {
                const unsigned long long vv0 = dup2(hreg[0][f]);
                const unsigned long long vv1 = dup2(hreg[1][f]);
                const ulonglong2* rw = (const ulonglong2*)&sRK[f * 4];
                #pragma unroll
                for (int h = 0; h < 4; h++) {
                    const ulonglong2 w = rw[h];
                    fma2(zp0[2 * h],     vv0, w.x);
                    fma2(zp0[2 * h + 1], vv0, w.y);
                    fma2(zp1[2 * h],     vv1, w.x);
                    fma2(zp1[2 * h + 1], vv1, w.y);
                }
            }
            // q=1..3: neighbors at +1,+96,+97 — UNCONDITIONAL (pads are zero).
            #pragma unroll
            for (int q = 1; q < 4; q++) {
                const int off = (q >> 1) * W96 + (q & 1);   // +1, +96, +97
                float4 h40 = make_float4(0.f, 0.f, 0.f, 0.f);
                float4 h41 = make_float4(0.f, 0.f, 0.f, 0.f);
                if (a0) h40 = *(const float4*)(hprev + (size_t)(p0 + off) * 4);
                if (a1) h41 = *(const float4*)(hprev + (size_t)(p1 + off) * 4);
                m[0][0] = fmaxf(m[0][0], h40.x); m[0][1] = fmaxf(m[0][1], h40.y);
                m[0][2] = fmaxf(m[0][2], h40.z); m[0][3] = fmaxf(m[0][3], h40.w);
                m[1][0] = fmaxf(m[1][0], h41.x); m[1][1] = fmaxf(m[1][1], h41.y);
                m[1][2] = fmaxf(m[1][2], h41.z); m[1][3] = fmaxf(m[1][3], h41.w);
                const float hv0[4] = {h40.x, h40.y, h40.z, h40.w};
                const float hv1[4] = {h41.x, h41.y, h41.z, h41.w};
                #pragma unroll
                for (int f = 0; f < 4; f++) {
                    const unsigned long long vv0 = dup2(hv0[f]);
                    const unsigned long long vv1 = dup2(hv1[f]);
                    const ulonglong2* rw = (const ulonglong2*)&sRK[(q * 4 + f) * 4];
                    #pragma unroll
                    for (int h = 0; h < 4; h++) {
                        const ulonglong2 w = rw[h];
                        fma2(zp0[2 * h],     vv0, w.x);
                        fma2(zp0[2 * h + 1], vv0, w.y);
                        fma2(zp1[2 * h],     vv1, w.x);
                        fma2(zp1[2 * h + 1], vv1, w.y);
                    }
                }
            }
        }

        // ---- gates (order i,f,g,o) + state update + h store, per position ----
        float* hnew = g_h[t & 1] + (size_t)b * SLOTS * FF;
        #pragma unroll
        for (int s = 0; s < 2; s++) {
            unsigned long long* zp = (s == 0) ? zp0 : zp1;
            const float2 a0v = unpack2(zp[0]), a1v = unpack2(zp[1]);
            const float2 b0v = unpack2(zp[2]), b1v = unpack2(zp[3]);
            const float2 c0v = unpack2(zp[4]), c1v = unpack2(zp[5]);
            const float2 d0v = unpack2(zp[6]), d1v = unpack2(zp[7]);
            const float zi[4] = {a0v.x, a0v.y, a1v.x, a1v.y};
            const float zf[4] = {b0v.x, b0v.y, b1v.x, b1v.y};
            const float zg[4] = {c0v.x, c0v.y, c1v.x, c1v.y};
            const float zo[4] = {d0v.x, d0v.y, d1v.x, d1v.y};
            #pragma unroll
            for (int f = 0; f < 4; f++) {
                const float ig = fsig(zi[f]);
                const float fg = fsig(zf[f]);
                const float gg = ftanh(zg[f]);
                const float og = fsig(zo[f]);
                const float c2 = fg * creg[s][f] + ig * gg;
                creg[s][f] = c2;
                hreg[s][f] = og * ftanh(c2);
            }
            const int  ps = (s == 0) ? p0 : p1;
            const bool as = (s == 0) ? a0 : a1;
            if (as)
                *(float4*)(hnew + (size_t)ps * 4) =
                    make_float4(hreg[s][0], hreg[s][1], hreg[s][2], hreg[s][3]);
        }

        // ---- maxpool(2x2) + dense contribution of h_{t-1}, per position ----
        if (t > 0) {
            #pragma unroll
            for (int s = 0; s < 2; s++) {
                const int  is = (s == 0) ? i0 : i1;
                const int  js = (s == 0) ? j0 : j1;
                const bool as = (s == 0) ? a0 : a1;
                if (as && ((is & 1) | (js & 1)) == 0 && is < 94 && js < 94) {
                    const int ph = is >> 1, pw = js >> 1;
                    const float4 w4 = *(const float4*)(dw +
                        ((((size_t)(t - 1) * PH + ph) * PW + pw) * 4));
                    dense_acc += m[s][0] * w4.x + m[s][1] * w4.y
                               + m[s][2] * w4.z + m[s][3] * w4.w;
                }
            }
        }

        __syncthreads();   // all h stores done before publish
        if (tid == 0)
            st_release(&g_flag[b][blk][0], base + (unsigned)(t + 1));

        // Stage step t+1's x-dependent work in the neighbor-skew shadow.
        if (t + 1 < TT)
            input_conv2(zp0, zp1, x, b, t + 1, i0, j0, a0, i1, j1, a1, sK, sB);
    }

    // Epilogue RAW: pool of h_{T-1}; own values in hreg, neighbors unconditional.
    if (tid == 0) {
        if (blk + 1 < NBLKX) wait_flag(&g_flag[b][blk + 1][0], base + TT);
    }
    __syncthreads();

    {
        const float* hlast = g_h[(TT - 1) & 1] + (size_t)b * SLOTS * FF;
        #pragma unroll
        for (int s = 0; s < 2; s++) {
            const int  is = (s == 0) ? i0 : i1;
            const int  js = (s == 0) ? j0 : j1;
            const int  ps = (s == 0) ? p0 : p1;
            const bool as = (s == 0) ? a0 : a1;
            if (as && ((is & 1) | (js & 1)) == 0 && is < 94 && js < 94) {
                float m0 = hreg[s][0], m1 = hreg[s][1], m2 = hreg[s][2], m3 = hreg[s][3];
                #pragma unroll
                for (int q = 1; q < 4; q++) {
                    const int off = (q >> 1) * W96 + (q & 1);
                    const float4 h4 = *(const float4*)(hlast + (size_t)(ps + off) * 4);
                    m0 = fmaxf(m0, h4.x); m1 = fmaxf(m1, h4.y);
                    m2 = fmaxf(m2, h4.z); m3 = fmaxf(m3, h4.w);
                }
                const int ph = is >> 1, pw = js >> 1;
                const float4 w4 = *(const float4*)(dw +
                    ((((size_t)(TT - 1) * PH + ph) * PW + pw) * 4));
                dense_acc += m0 * w4.x + m1 * w4.y + m2 * w4.z + m3 * w4.w;
            }
        }
    }

    // Deterministic block reduction -> one scratch write per CTA.
    #pragma unroll
    for (int off = 16; off > 0; off >>= 1)
        dense_acc += __shfl_down_sync(0xFFFFFFFFu, dense_acc, off);
    if ((tid & 31) == 0) warpsum[tid >> 5] = dense_acc;
    __syncthreads();
    if (tid == 0) {
        float s = 0.f;
        #pragma unroll
        for (int w = 0; w < NTHREADS / 32; w++) s += warpsum[w];
        g_scratch[b * NBLKX + blk] = s;

        // Per-batch completion: last CTA of batch b emits out[b].
        __threadfence();
        const unsigned old = atomicAdd(&g_done[b], 1u);
        if (old == (unsigned)(NBLKX - 1)) {
            atomicExch(&g_done[b], 0u);   // self-reset for next replay
            __threadfence();
            float acc = 0.f;
            for (int k = 0; k < NBLKX; k++) acc += g_scratch[b * NBLKX + k];
            out[b] = acc + db[0];
        }
    }
}

extern "C" void kernel_launch(void* const* d_in, const int* in_sizes, int n_in,
                              void* d_out, int out_size) {
    const float*  x    = (const float*)d_in[0];
    const float4* Kw   = (const float4*)d_in[1];
    const float4* RKw  = (const float4*)d_in[2];
    const float4* bias = (const float4*)d_in[3];
    const float*  dw   = (const float*)d_in[4];
    const float*  db   = (const float*)d_in[5];
    float* out = (float*)d_out;

    dim3 grid(NBLKX, BB);
    persistent_kernel<<<grid, NTHREADS>>>(x, Kw, RKw, bias, dw, db, out);
}